// round 1
// baseline (speedup 1.0000x reference)
#include <cuda_runtime.h>
#include <math_constants.h>

#define HW_DIM 10
#define NUM_DEV 50
#define NUM_INT 101
#define ODIM 30

__global__ __launch_bounds__(32, 1)
void mhn_kernel(const float* __restrict__ x,
                const float* __restrict__ hw,
                const float* __restrict__ hw_emb,
                const float* __restrict__ expert_emb,
                float* __restrict__ out)
{
    const int lane = threadIdx.x;
    __shared__ float gate[NUM_DEV];

    // Broadcast-load hw into registers (10 floats, L1-cached broadcast)
    float h[HW_DIM];
#pragma unroll
    for (int j = 0; j < HW_DIM; ++j) h[j] = hw[j];

    const float inv_sqrt = 0.31622776601683794f; // 1/sqrt(10)

    // Each lane: experts lane and lane+32
    float s0, s1;
    {
        float d = 0.f;
        const float* he = hw_emb + lane * HW_DIM;
#pragma unroll
        for (int j = 0; j < HW_DIM; ++j) d = fmaf(h[j], he[j], d);
        s0 = sinf(d * inv_sqrt);
    }
    {
        const int e = lane + 32;
        if (e < NUM_DEV) {
            float d = 0.f;
            const float* he = hw_emb + e * HW_DIM;
#pragma unroll
            for (int j = 0; j < HW_DIM; ++j) d = fmaf(h[j], he[j], d);
            s1 = sinf(d * inv_sqrt);
        } else {
            s1 = -CUDART_INF_F;
        }
    }

    // Warp max-reduce over 50 logical values
    float m = fmaxf(s0, s1);
#pragma unroll
    for (int o = 16; o > 0; o >>= 1)
        m = fmaxf(m, __shfl_xor_sync(0xffffffffu, m, o));

    const float e0 = expf(s0 - m);
    const float e1 = (lane + 32 < NUM_DEV) ? expf(s1 - m) : 0.f;

    float sum = e0 + e1;
#pragma unroll
    for (int o = 16; o > 0; o >>= 1)
        sum += __shfl_xor_sync(0xffffffffu, sum, o);

    const float rs = 1.f / sum;
    gate[lane] = e0 * rs;
    if (lane + 32 < NUM_DEV) gate[lane + 32] = e1 * rs;
    __syncwarp();

    // Data-dependent interval index (round-to-nearest-even like jnp.round)
    const int idx = (int)rintf(x[0] * (float)(NUM_INT - 1));

    // Lanes 0..29: one output dim each; coalesced across lanes per expert
    if (lane < ODIM) {
        const float* base = expert_emb + (size_t)idx * ODIM + lane;
        float acc = 0.f;
#pragma unroll
        for (int e = 0; e < NUM_DEV; ++e)
            acc = fmaf(gate[e], base[(size_t)e * (NUM_INT * ODIM)], acc);
        out[lane] = acc;
    }
}

extern "C" void kernel_launch(void* const* d_in, const int* in_sizes, int n_in,
                              void* d_out, int out_size)
{
    const float* x          = (const float*)d_in[0];
    const float* hw         = (const float*)d_in[1];
    const float* hw_emb     = (const float*)d_in[2];
    const float* expert_emb = (const float*)d_in[3];
    float* out = (float*)d_out;

    mhn_kernel<<<1, 32>>>(x, hw, hw_emb, expert_emb, out);
}